// round 14
// baseline (speedup 1.0000x reference)
#include <cuda_runtime.h>
#include <cstdint>

#define NN   100000
#define EMAX 1600000
#define F    16

typedef unsigned long long ull;

// ---------------- scratch (static __device__, no allocs) ----------------
__device__ int g_deg[NN];
__device__ int g_cur[NN];
__device__ int g_off[NN + 1];
__device__ ull g_sdesc[128];     // decoupled-lookback descriptors: (stat<<32)|val
__device__ __align__(16) int2  g_sd[EMAX];                 // sorted (src,dst)
__device__ __align__(16) float g_eas[(size_t)EMAX * 8];    // sorted edge_attr
__device__ __align__(16) float g_P2[NN * F];               // conv2 src-partial (bias+src rows)
__device__ __align__(16) float g_h1[NN * F];
__device__ __align__(16) float g_h2[NN * F];
__device__ __align__(16) float g_stage[1792];              // weight staging

// ---------------- all weights in ONE constant array ----------------
#define OC1W1 0      // 256
#define OC1B1 256    // 16
#define OC1W2 272    // 256
#define OC1B2 528    // 16
#define OC2W1 544    // 640
#define OC2B1 1184   // 16
#define OC2W2 1200   // 256
#define OC2B2 1456   // 16
#define OCLW1 1472   // 256
#define OCLB1 1728   // 16
#define OCLW2 1744   // 16
#define OCLB2 1760   // 1
#define CWTOT 1761
__constant__ __align__(16) float cw[1792];

// ---------------- f32x2 packed helpers ----------------
__device__ __forceinline__ ull pk2(float a, float b) {
    ull r; asm("mov.b64 %0, {%1, %2};" : "=l"(r) : "f"(a), "f"(b)); return r;
}
__device__ __forceinline__ ull bcast2(float a) {
    ull r; asm("mov.b64 %0, {%1, %1};" : "=l"(r) : "f"(a)); return r;
}
__device__ __forceinline__ void upk2(ull v, float& a, float& b) {
    asm("mov.b64 {%0, %1}, %2;" : "=f"(a), "=f"(b) : "l"(v));
}
__device__ __forceinline__ ull fma2(ull a, ull b, ull c) {
    ull d; asm("fma.rn.f32x2 %0, %1, %2, %3;" : "=l"(d) : "l"(a), "l"(b), "l"(c)); return d;
}

// ---------------- per-block int64 detection ----------------
__device__ __forceinline__ bool block_idx64(const void* ei, int N, int* sflag) {
    if (threadIdx.x == 0) {
        const long long* p64 = (const long long*)ei;
        bool ok = true;
#pragma unroll
        for (int k = 0; k < 4; k++) {
            long long v = p64[k];
            if (v < 0 || v >= N) ok = false;
        }
        *sflag = ok ? 1 : 0;
    }
    __syncthreads();
    return *sflag != 0;
}

// ---------------- weight staging: 12 buffers -> one device array ----------------
__global__ void __launch_bounds__(256) stage_weights_kernel(
    const float* w0, const float* w1, const float* w2, const float* w3,
    const float* w4, const float* w5, const float* w6, const float* w7,
    const float* w8, const float* w9, const float* w10, const float* w11)
{
    int t = threadIdx.x;
    for (int i = t; i < 256; i += 256) g_stage[OC1W1 + i] = w0[i];
    if (t < 16)  g_stage[OC1B1 + t] = w1[t];
    for (int i = t; i < 256; i += 256) g_stage[OC1W2 + i] = w2[i];
    if (t < 16)  g_stage[OC1B2 + t] = w3[t];
    for (int i = t; i < 640; i += 256) g_stage[OC2W1 + i] = w4[i];
    if (t < 16)  g_stage[OC2B1 + t] = w5[t];
    for (int i = t; i < 256; i += 256) g_stage[OC2W2 + i] = w6[i];
    if (t < 16)  g_stage[OC2B2 + t] = w7[t];
    for (int i = t; i < 256; i += 256) g_stage[OCLW1 + i] = w8[i];
    if (t < 16)  g_stage[OCLB1 + t] = w9[t];
    if (t < 16)  g_stage[OCLW2 + t] = w10[t];
    if (t == 0)  g_stage[OCLB2] = w11[0];
}

// ---------------- zeroing kernels ----------------
__global__ void zero_h_kernel(int N) {
    int i = blockIdx.x * blockDim.x + threadIdx.x;
    int n4 = N * 4;
    if (i < n4) {
        reinterpret_cast<float4*>(g_h1)[i] = make_float4(0.f, 0.f, 0.f, 0.f);
        reinterpret_cast<float4*>(g_h2)[i] = make_float4(0.f, 0.f, 0.f, 0.f);
    }
}

__global__ void zero_deg_kernel(int N) {
    int i = blockIdx.x * blockDim.x + threadIdx.x;
    if (i < N) g_deg[i] = 0;
    if (i < 128) g_sdesc[i] = 0ULL;   // reset lookback descriptors
}

__global__ void hist_kernel(const void* __restrict__ ei, int E, int N) {
    __shared__ int sflag;
    bool idx64 = block_idx64(ei, N, &sflag);
    int e = blockIdx.x * blockDim.x + threadIdx.x;
    if (e >= E) return;
    int s = idx64 ? (int)((const long long*)ei)[e] : ((const int*)ei)[e];
    atomicAdd(&g_deg[s], 1);
}

// ---------------- single-pass decoupled-lookback scan ----------------
// replaces scan_blocks + scan_tops + add_offsets
__global__ void __launch_bounds__(1024) scan_fused_kernel(int n) {
    __shared__ int wsum[32];
    __shared__ int sbase;
    int bid  = blockIdx.x;
    int i    = bid * 1024 + threadIdx.x;
    int lane = threadIdx.x & 31;
    int wid  = threadIdx.x >> 5;

    int v = (i < n) ? g_deg[i] : 0;
    int s = v;
#pragma unroll
    for (int o = 1; o < 32; o <<= 1) {
        int t = __shfl_up_sync(~0u, s, o);
        if (lane >= o) s += t;
    }
    if (lane == 31) wsum[wid] = s;
    __syncthreads();
    if (wid == 0) {
        int ws = wsum[lane];
#pragma unroll
        for (int o = 1; o < 32; o <<= 1) {
            int t = __shfl_up_sync(~0u, ws, o);
            if (lane >= o) ws += t;
        }
        wsum[lane] = ws;
    }
    __syncthreads();
    int excl  = s - v + (wid > 0 ? wsum[wid - 1] : 0);
    int total = wsum[31];

    // one thread per block handles publish + lookback
    if (threadIdx.x == 0) {
        if (bid == 0) {
            atomicExch(&g_sdesc[0], (2ULL << 32) | (unsigned)total);
            sbase = 0;
        } else {
            // publish aggregate
            atomicExch(&g_sdesc[bid], (1ULL << 32) | (unsigned)total);
            // lookback
            int pre = 0;
            int j = bid - 1;
            while (true) {
                ull d = atomicAdd(&g_sdesc[j], 0ULL);
                unsigned st = (unsigned)(d >> 32);
                if (st == 0) continue;            // not published yet; poll
                pre += (int)(unsigned)d;
                if (st == 2) break;               // hit an inclusive prefix
                j--;
            }
            atomicExch(&g_sdesc[bid], (2ULL << 32) | (unsigned)(pre + total));
            sbase = pre;
        }
    }
    __syncthreads();
    int base = sbase;
    if (i < n) {
        int o = excl + base;
        g_off[i] = o;
        g_cur[i] = o;
    }
}

__global__ void scatter_kernel(const void* __restrict__ ei,
                               const float* __restrict__ ea, int E, int N) {
    __shared__ int sflag;
    bool idx64 = block_idx64(ei, N, &sflag);
    int e = blockIdx.x * blockDim.x + threadIdx.x;
    if (e >= E) return;
    int s, d;
    if (idx64) {
        const long long* p = (const long long*)ei;
        s = (int)p[e]; d = (int)p[(size_t)E + e];
    } else {
        const int* p = (const int*)ei;
        s = p[e]; d = p[(size_t)E + e];
    }
    int pos = atomicAdd(&g_cur[s], 1);
    g_sd[pos] = make_int2(s, d);
    float4 a0 = *(const float4*)(ea + (size_t)e * 8);
    float4 a1 = *(const float4*)(ea + (size_t)e * 8 + 4);
    *(float4*)(g_eas + (size_t)pos * 8)     = a0;
    *(float4*)(g_eas + (size_t)pos * 8 + 4) = a1;
}

// ---------------- P2: conv2 src-partial per node ----------------
__global__ void __launch_bounds__(256) p2_kernel(int N) {
    int n = blockIdx.x * blockDim.x + threadIdx.x;
    if (n >= N) return;
    const ull* w1p = reinterpret_cast<const ull*>(cw + OC2W1);
    ull H[8];
#pragma unroll
    for (int k = 0; k < 8; k++) H[k] = pk2(cw[OC2B1 + 2*k], cw[OC2B1 + 2*k+1]);
    const float4* ph = (const float4*)(g_h1 + (size_t)n * F);
#pragma unroll
    for (int q = 0; q < 4; q++) {
        float4 v = ph[q];
        float hv[4] = {v.x, v.y, v.z, v.w};
#pragma unroll
        for (int r = 0; r < 4; r++) {
            ull vv = bcast2(hv[r]);
            int i = q * 4 + r;
#pragma unroll
            for (int k = 0; k < 8; k++) H[k] = fma2(vv, w1p[i*8 + k], H[k]);
        }
    }
    ull* out = (ull*)(g_P2 + (size_t)n * F);
#pragma unroll
    for (int k = 0; k < 8; k++) out[k] = H[k];
}

// ---------------- warp-segmented max (shfl scan) + tail atomics ----------------
__device__ __forceinline__ void seg_max_commit(int s, float* o, float* hout) {
    int lane = threadIdx.x & 31;
#pragma unroll
    for (int off = 1; off < 32; off <<= 1) {
        int so = __shfl_up_sync(~0u, s, off);
        bool merge = (lane >= off) && (so == s);
#pragma unroll
        for (int f = 0; f < F; f++) {
            float v = __shfl_up_sync(~0u, o[f], off);
            if (merge) o[f] = fmaxf(o[f], v);
        }
    }
    int snext = __shfl_down_sync(~0u, s, 1);
    bool tail = (lane == 31) || (snext != s);
    if (tail) {
        int* hp = (int*)(hout + (size_t)s * F);
#pragma unroll
        for (int f = 0; f < F; f++)
            atomicMax(hp + f, __float_as_int(fmaxf(o[f], 0.f)));
    }
}

// ---------------- conv edge kernels: one lane = one sorted edge ----------------
__global__ void __launch_bounds__(256) conv1_edge_kernel(const float* __restrict__ x, int E) {
    int p = blockIdx.x * blockDim.x + threadIdx.x;
    p = min(p, E - 1);   // duplicates harmless for max

    const ull* w1p = reinterpret_cast<const ull*>(cw + OC1W1);
    const ull* w2p = reinterpret_cast<const ull*>(cw + OC1W2);

    int2 sd = g_sd[p];
    float4 xi = *(const float4*)(x + (size_t)sd.x * 4);
    float4 xj = *(const float4*)(x + (size_t)sd.y * 4);
    float4 a0 = *(const float4*)(g_eas + (size_t)p * 8);
    float4 a1 = *(const float4*)(g_eas + (size_t)p * 8 + 4);

    ull H[8];
#pragma unroll
    for (int k = 0; k < 8; k++) H[k] = pk2(cw[OC1B1 + 2*k], cw[OC1B1 + 2*k+1]);

    float in[16] = {xi.x, xi.y, xi.z, xi.w, xj.x, xj.y, xj.z, xj.w,
                    a0.x, a0.y, a0.z, a0.w, a1.x, a1.y, a1.z, a1.w};
#pragma unroll
    for (int i = 0; i < 16; i++) {
        ull vv = bcast2(in[i]);
#pragma unroll
        for (int k = 0; k < 8; k++) H[k] = fma2(vv, w1p[i*8 + k], H[k]);
    }

    ull O[8];
#pragma unroll
    for (int k = 0; k < 8; k++) O[k] = pk2(cw[OC1B2 + 2*k], cw[OC1B2 + 2*k+1]);
#pragma unroll
    for (int k = 0; k < 8; k++) {
        float a, b; upk2(H[k], a, b);
        a = fmaxf(a, 0.f); b = fmaxf(b, 0.f);
        ull va = bcast2(a), vb = bcast2(b);
#pragma unroll
        for (int m = 0; m < 8; m++) O[m] = fma2(va, w2p[(2*k)*8 + m], O[m]);
#pragma unroll
        for (int m = 0; m < 8; m++) O[m] = fma2(vb, w2p[(2*k+1)*8 + m], O[m]);
    }
    float o[F];
#pragma unroll
    for (int m = 0; m < 8; m++) upk2(O[m], o[2*m], o[2*m+1]);

    seg_max_commit(sd.x, o, g_h1);
}

__global__ void __launch_bounds__(256) conv2_edge_kernel(int E) {
    int p = blockIdx.x * blockDim.x + threadIdx.x;
    p = min(p, E - 1);

    const ull* w1p = reinterpret_cast<const ull*>(cw + OC2W1);
    const ull* w2p = reinterpret_cast<const ull*>(cw + OC2W2);

    int2 sd = g_sd[p];
    ull H[8];
    {
        const ull* Pp = (const ull*)(g_P2 + (size_t)sd.x * F);
#pragma unroll
        for (int k = 0; k < 8; k++) H[k] = Pp[k];
    }
    float in[24];
    {
        const float4* pd = (const float4*)(g_h1 + (size_t)sd.y * F);
#pragma unroll
        for (int q = 0; q < 4; q++) {
            float4 v = pd[q];
            in[q*4+0] = v.x; in[q*4+1] = v.y; in[q*4+2] = v.z; in[q*4+3] = v.w;
        }
        float4 a0 = *(const float4*)(g_eas + (size_t)p * 8);
        float4 a1 = *(const float4*)(g_eas + (size_t)p * 8 + 4);
        in[16] = a0.x; in[17] = a0.y; in[18] = a0.z; in[19] = a0.w;
        in[20] = a1.x; in[21] = a1.y; in[22] = a1.z; in[23] = a1.w;
    }
#pragma unroll
    for (int i = 0; i < 24; i++) {
        ull vv = bcast2(in[i]);
#pragma unroll
        for (int k = 0; k < 8; k++) H[k] = fma2(vv, w1p[(16+i)*8 + k], H[k]);
    }

    ull O[8];
#pragma unroll
    for (int k = 0; k < 8; k++) O[k] = pk2(cw[OC2B2 + 2*k], cw[OC2B2 + 2*k+1]);
#pragma unroll
    for (int k = 0; k < 8; k++) {
        float a, b; upk2(H[k], a, b);
        a = fmaxf(a, 0.f); b = fmaxf(b, 0.f);
        ull va = bcast2(a), vb = bcast2(b);
#pragma unroll
        for (int m = 0; m < 8; m++) O[m] = fma2(va, w2p[(2*k)*8 + m], O[m]);
#pragma unroll
        for (int m = 0; m < 8; m++) O[m] = fma2(vb, w2p[(2*k+1)*8 + m], O[m]);
    }
    float o[F];
#pragma unroll
    for (int m = 0; m < 8; m++) upk2(O[m], o[2*m], o[2*m+1]);

    seg_max_commit(sd.x, o, g_h2);
}

// ---------------- final node MLP (packed) ----------------
__global__ void __launch_bounds__(256) node_mlp_kernel(float* __restrict__ out, int n) {
    int i = blockIdx.x * blockDim.x + threadIdx.x;
    if (i >= n) return;

    const ull* w1p = reinterpret_cast<const ull*>(cw + OCLW1);

    ull H[8];
#pragma unroll
    for (int k = 0; k < 8; k++) H[k] = pk2(cw[OCLB1 + 2*k], cw[OCLB1 + 2*k+1]);

    const float4* ph = (const float4*)(g_h2 + (size_t)i * F);
#pragma unroll
    for (int q = 0; q < 4; q++) {
        float4 v = ph[q];
        float hv[4] = {v.x, v.y, v.z, v.w};
#pragma unroll
        for (int r = 0; r < 4; r++) {
            ull vv = bcast2(hv[r]);
            int kk = q * 4 + r;
#pragma unroll
            for (int k = 0; k < 8; k++) H[k] = fma2(vv, w1p[kk*8 + k], H[k]);
        }
    }

    float acc = cw[OCLB2];
#pragma unroll
    for (int k = 0; k < 8; k++) {
        float a, b; upk2(H[k], a, b);
        acc += fmaxf(a, 0.f) * cw[OCLW2 + 2*k] + fmaxf(b, 0.f) * cw[OCLW2 + 2*k+1];
    }
    out[i] = acc;
}

// ---------------- launch: fork-join to overlap weight/zero chain with edge chain ----------------
extern "C" void kernel_launch(void* const* d_in, const int* in_sizes, int n_in,
                              void* d_out, int out_size)
{
    const float* x  = (const float*)d_in[0];
    const void*  ei = d_in[1];
    const float* ea = (const float*)d_in[2];

    int N = in_sizes[0] / 4;   // x is [N,4]
    int E = in_sizes[2] / 8;   // edge_attr is [E,8]
    float* out = (float*)d_out;

    static cudaStream_t sB = nullptr;
    static cudaEvent_t  ev0 = nullptr, evB = nullptr;
    if (sB == nullptr) {
        cudaStreamCreateWithFlags(&sB, cudaStreamNonBlocking);
        cudaEventCreateWithFlags(&ev0, cudaEventDisableTiming);
        cudaEventCreateWithFlags(&evB, cudaEventDisableTiming);
    }

    int eblocks = (E + 255) / 256;
    int sblocks = (N + 1023) / 1024;

    // fork: edge pipeline on sB
    cudaEventRecord(ev0, 0);
    cudaStreamWaitEvent(sB, ev0, 0);
    zero_deg_kernel<<<(N + 255) / 256, 256, 0, sB>>>(N);
    hist_kernel<<<eblocks, 256, 0, sB>>>(ei, E, N);
    scan_fused_kernel<<<sblocks, 1024, 0, sB>>>(N);
    scatter_kernel<<<eblocks, 256, 0, sB>>>(ei, ea, E, N);
    cudaEventRecord(evB, sB);

    // main stream: weights + h zeroing (independent of edge pipeline)
    stage_weights_kernel<<<1, 256>>>(
        (const float*)d_in[3],  (const float*)d_in[4],  (const float*)d_in[5],
        (const float*)d_in[6],  (const float*)d_in[7],  (const float*)d_in[8],
        (const float*)d_in[9],  (const float*)d_in[10], (const float*)d_in[11],
        (const float*)d_in[12], (const float*)d_in[13], (const float*)d_in[14]);
    void* stage_addr = nullptr;
    cudaGetSymbolAddress(&stage_addr, g_stage);
    cudaMemcpyToSymbolAsync(cw, stage_addr, CWTOT * sizeof(float), 0,
                            cudaMemcpyDeviceToDevice);
    zero_h_kernel<<<(N * 4 + 255) / 256, 256>>>(N);

    // join
    cudaStreamWaitEvent(0, evB, 0);

    conv1_edge_kernel<<<eblocks, 256>>>(x, E);
    p2_kernel<<<(N + 255) / 256, 256>>>(N);
    conv2_edge_kernel<<<eblocks, 256>>>(E);
    node_mlp_kernel<<<(N + 255) / 256, 256>>>(out, N);
}